// round 2
// baseline (speedup 1.0000x reference)
#include <cuda_runtime.h>

// Problem constants
#define BSZ   4096
#define PSZ   32
#define EMB   128
// H = concat(g1,g2,g3), each group emits 256 dims (out1|out2)
#define HDIM  768

// Scratch: intermediate H [B, 768] (12.6 MB) — __device__ global (no allocs allowed)
__device__ float g_H[BSZ * HDIM];

__device__ __forceinline__ float4 relu_step(float4 x, float4 w, float4 y, float4 bm) {
    float4 r;
    r.x = fmaxf(fmaf(x.x * w.x, y.x, bm.x), 0.f);
    r.y = fmaxf(fmaf(x.y * w.y, y.y, bm.y), 0.f);
    r.z = fmaxf(fmaf(x.z * w.z, y.z, bm.z), 0.f);
    r.w = fmaxf(fmaf(x.w * w.w, y.w, bm.w), 0.f);
    return r;
}

// One block per batch row b, for one path-length group L.
// 8 warps; warp w handles paths p = w, w+8, w+16, w+24. Lane owns dims [4*lane, 4*lane+4).
template<int L>
__global__ __launch_bounds__(256) void path_kernel(
    const int*   __restrict__ ents,    // [B,P,L+1]
    const int*   __restrict__ mids,    // [B,P,L]
    const float* __restrict__ counts,  // [B,P]
    const float* __restrict__ E,       // [100000,128]
    const float* __restrict__ Wm,      // [3,128]
    const float* __restrict__ Bm,      // [3,128]
    int gofs)                          // column offset into H (0 / 256 / 512)
{
    __shared__ float sW[3 * EMB];
    __shared__ float sB[3 * EMB];
    __shared__ float sAcc[8][256];
    __shared__ float sCnt[8];

    const int b    = blockIdx.x;
    const int tid  = threadIdx.x;
    const int wid  = tid >> 5;
    const int lane = tid & 31;

    for (int i = tid; i < 3 * EMB; i += 256) { sW[i] = Wm[i]; sB[i] = Bm[i]; }
    __syncthreads();

    float4 a1 = make_float4(0.f, 0.f, 0.f, 0.f);
    float4 a2 = make_float4(0.f, 0.f, 0.f, 0.f);
    float  cs = 0.f;

    #pragma unroll
    for (int pp = 0; pp < 4; pp++) {
        const int  p    = wid + pp * 8;
        const long base = (long)b * PSZ + p;
        const int* ep   = ents + base * (L + 1);
        const int* mp   = mids + base * L;
        const float cnt = counts[base];

        int e[L + 1], m[L];
        #pragma unroll
        for (int i = 0; i <= L; i++) e[i] = ep[i];
        #pragma unroll
        for (int i = 0; i < L; i++)  m[i] = mp[i];

        // Prefetch all embedding rows for this path (independent L2 gathers)
        float4 rows[L + 1];
        #pragma unroll
        for (int i = 0; i <= L; i++)
            rows[i] = *(const float4*)(E + (long)e[i] * EMB + lane * 4);

        // forward
        float4 x = rows[0];
        #pragma unroll
        for (int i = 0; i < L; i++) {
            float4 w  = *(const float4*)(sW + m[i] * EMB + lane * 4);
            float4 bb = *(const float4*)(sB + m[i] * EMB + lane * 4);
            x = relu_step(x, w, rows[i + 1], bb);
        }
        const float4 o1 = x;

        // backward: both the start x and the (stale) y are E[ents[L]]
        const float4 yl = rows[L];
        x = yl;
        #pragma unroll
        for (int i = L - 1; i >= 0; i--) {
            float4 w  = *(const float4*)(sW + m[i] * EMB + lane * 4);
            float4 bb = *(const float4*)(sB + m[i] * EMB + lane * 4);
            x = relu_step(x, w, yl, bb);
        }

        a1.x += cnt * o1.x; a1.y += cnt * o1.y; a1.z += cnt * o1.z; a1.w += cnt * o1.w;
        a2.x += cnt * x.x;  a2.y += cnt * x.y;  a2.z += cnt * x.z;  a2.w += cnt * x.w;
        cs   += cnt;
    }

    ((float4*)sAcc[wid])[lane]         = a1;   // dims 0..127  (out1)
    ((float4*)(sAcc[wid] + 128))[lane] = a2;   // dims 128..255 (out2)
    if (lane == 0) sCnt[wid] = cs;
    __syncthreads();

    // Deterministic tree reduce across the 8 warps
    float s = 0.f, csum = 0.f;
    #pragma unroll
    for (int w = 0; w < 8; w++) { s += sAcc[w][tid]; csum += sCnt[w]; }
    g_H[(long)b * HDIM + gofs + tid] = s / csum;
}

// MLP head: 32 batch rows per block, 256 threads, 128 blocks (one wave).
// Phase A: h1 = relu(H @ W1 + b1)   [32,128]  (K=768 streamed in 4 chunks of 192)
// Phase B: h2 = relu(h1 @ W2 + b2)  [32,32]
// Phase C: out = h2 @ W3 + b3       [32,1]
__global__ __launch_bounds__(256) void mlp_kernel(
    const float* __restrict__ W1, const float* __restrict__ b1,
    const float* __restrict__ W2, const float* __restrict__ b2,
    const float* __restrict__ W3, const float* __restrict__ b3,
    float* __restrict__ out)
{
    __shared__ float sH[32][192];   // 24 KB  (K-chunk of H tile)
    __shared__ float sh1[32][EMB];  // 16 KB
    __shared__ float sh2[32][32];   //  4 KB

    const int b0  = blockIdx.x * 32;
    const int tid = threadIdx.x;

    // Phase A: thread = (col c, 16 rows)
    const int c     = tid & 127;
    const int rbase = (tid >> 7) * 16;
    float acc[16];
    const float bias1 = b1[c];
    #pragma unroll
    for (int r = 0; r < 16; r++) acc[r] = bias1;

    for (int kb = 0; kb < 4; kb++) {
        __syncthreads();
        for (int i = tid; i < 32 * 48; i += 256) {
            const int r = i / 48, c4 = i % 48;
            ((float4*)&sH[r][0])[c4] =
                *(const float4*)(g_H + (long)(b0 + r) * HDIM + kb * 192 + c4 * 4);
        }
        __syncthreads();
        #pragma unroll 4
        for (int kk = 0; kk < 192; kk++) {
            const float w = W1[(kb * 192 + kk) * 128 + c];  // coalesced across threads
            #pragma unroll
            for (int r = 0; r < 16; r++) acc[r] = fmaf(sH[rbase + r][kk], w, acc[r]);
        }
    }
    #pragma unroll
    for (int r = 0; r < 16; r++) sh1[rbase + r][c] = fmaxf(acc[r], 0.f);
    __syncthreads();

    // Phase B
    {
        const int c2 = tid & 31;
        const int r0 = tid >> 5;   // 0..7
        #pragma unroll
        for (int rr = 0; rr < 4; rr++) {
            const int r = r0 + rr * 8;
            float a = b2[c2];
            #pragma unroll 8
            for (int k = 0; k < 128; k++) a = fmaf(sh1[r][k], W2[k * 32 + c2], a);
            sh2[r][c2] = fmaxf(a, 0.f);
        }
    }
    __syncthreads();

    // Phase C
    if (tid < 32) {
        float a = b3[0];
        #pragma unroll
        for (int k = 0; k < 32; k++) a = fmaf(sh2[tid][k], W3[k], a);
        out[b0 + tid] = a;
    }
}

extern "C" void kernel_launch(void* const* d_in, const int* in_sizes, int n_in,
                              void* d_out, int out_size)
{
    // Detect input ordering at runtime:
    //  dict order:      ent1,mid1,counts1, ent2,mid2,counts2, ent3,mid3,counts3, ...
    //  signature order: ent1,mid1, ent2,mid2, ent3,mid3, counts1,counts2,counts3, ...
    // in_sizes[2] = 131072 (counts1, B*P) in dict order; 393216 (ent2) in signature order.
    const bool dictOrder = (in_sizes[2] == BSZ * PSZ);

    const int *ent1, *mid1, *ent2, *mid2, *ent3, *mid3;
    const float *c1, *c2, *c3;
    if (dictOrder) {
        ent1 = (const int*)d_in[0]; mid1 = (const int*)d_in[1]; c1 = (const float*)d_in[2];
        ent2 = (const int*)d_in[3]; mid2 = (const int*)d_in[4]; c2 = (const float*)d_in[5];
        ent3 = (const int*)d_in[6]; mid3 = (const int*)d_in[7]; c3 = (const float*)d_in[8];
    } else {
        ent1 = (const int*)d_in[0]; mid1 = (const int*)d_in[1];
        ent2 = (const int*)d_in[2]; mid2 = (const int*)d_in[3];
        ent3 = (const int*)d_in[4]; mid3 = (const int*)d_in[5];
        c1 = (const float*)d_in[6]; c2 = (const float*)d_in[7]; c3 = (const float*)d_in[8];
    }
    const float* E  = (const float*)d_in[9];
    const float* Wm = (const float*)d_in[10];
    const float* Bm = (const float*)d_in[11];
    const float* W1 = (const float*)d_in[12];
    const float* b1 = (const float*)d_in[13];
    const float* W2 = (const float*)d_in[14];
    const float* b2 = (const float*)d_in[15];
    const float* W3 = (const float*)d_in[16];
    const float* b3 = (const float*)d_in[17];

    path_kernel<1><<<BSZ, 256>>>(ent1, mid1, c1, E, Wm, Bm, 0);
    path_kernel<2><<<BSZ, 256>>>(ent2, mid2, c2, E, Wm, Bm, 256);
    path_kernel<3><<<BSZ, 256>>>(ent3, mid3, c3, E, Wm, Bm, 512);
    mlp_kernel<<<BSZ / 32, 256>>>(W1, b1, W2, b2, W3, b3, (float*)d_out);
}

// round 3
// speedup vs baseline: 1.4072x; 1.4072x over previous
#include <cuda_runtime.h>

// Problem constants
#define BSZ   4096
#define PSZ   32
#define EMB   128
#define HDIM  768
#define MROWS 16            // batch rows per MLP block

// Scratch: intermediate H [B, 768] (12.6 MB)
__device__ float g_H[BSZ * HDIM];

__device__ __forceinline__ float4 relu_step(float4 x, float4 w, float4 y, float4 bm) {
    float4 r;
    r.x = fmaxf(fmaf(x.x * w.x, y.x, bm.x), 0.f);
    r.y = fmaxf(fmaf(x.y * w.y, y.y, bm.y), 0.f);
    r.z = fmaxf(fmaf(x.z * w.z, y.z, bm.z), 0.f);
    r.w = fmaxf(fmaf(x.w * w.w, y.w, bm.w), 0.f);
    return r;
}

// One block per batch row b, for one path-length group L.
// 8 warps; warp w handles paths p = w, w+8, w+16, w+24 with 1-path lookahead
// prefetch of embedding rows. Lane owns dims [4*lane, 4*lane+4).
template<int L>
__global__ __launch_bounds__(256) void path_kernel(
    const int*   __restrict__ ents,    // [B,P,L+1]
    const int*   __restrict__ mids,    // [B,P,L]
    const float* __restrict__ counts,  // [B,P]
    const float* __restrict__ E,       // [100000,128]
    const float* __restrict__ Wm,      // [3,128]
    const float* __restrict__ Bm,      // [3,128]
    int gofs)
{
    __shared__ float sW[3 * EMB];
    __shared__ float sB[3 * EMB];
    __shared__ float sAcc[8][256];
    __shared__ float sCnt[8];

    const int b    = blockIdx.x;
    const int tid  = threadIdx.x;
    const int wid  = tid >> 5;
    const int lane = tid & 31;

    for (int i = tid; i < 3 * EMB; i += 256) { sW[i] = Wm[i]; sB[i] = Bm[i]; }
    __syncthreads();

    // Hoist all indices + counts for this warp's 4 paths
    int   e[4][L + 1];
    int   m[4][L];
    float cnt[4];
    #pragma unroll
    for (int pp = 0; pp < 4; pp++) {
        const long base = (long)b * PSZ + (wid + pp * 8);
        const int* ep = ents + base * (L + 1);
        const int* mp = mids + base * L;
        #pragma unroll
        for (int i = 0; i <= L; i++) e[pp][i] = ep[i];
        #pragma unroll
        for (int i = 0; i < L; i++)  m[pp][i] = mp[i];
        cnt[pp] = counts[base];
    }

    float4 a1 = make_float4(0.f, 0.f, 0.f, 0.f);
    float4 a2 = make_float4(0.f, 0.f, 0.f, 0.f);
    float  cs = 0.f;

    // Double-buffered embedding-row gathers: buf[pp&1] = rows of path pp
    float4 buf[2][L + 1];
    #pragma unroll
    for (int i = 0; i <= L; i++)
        buf[0][i] = *(const float4*)(E + (long)e[0][i] * EMB + lane * 4);

    #pragma unroll
    for (int pp = 0; pp < 4; pp++) {
        // Prefetch next path's rows before using this path's
        if (pp < 3) {
            #pragma unroll
            for (int i = 0; i <= L; i++)
                buf[(pp + 1) & 1][i] =
                    *(const float4*)(E + (long)e[pp + 1][i] * EMB + lane * 4);
        }
        float4 (&rows)[L + 1] = buf[pp & 1];

        // forward
        float4 x = rows[0];
        #pragma unroll
        for (int i = 0; i < L; i++) {
            float4 w  = *(const float4*)(sW + m[pp][i] * EMB + lane * 4);
            float4 bb = *(const float4*)(sB + m[pp][i] * EMB + lane * 4);
            x = relu_step(x, w, rows[i + 1], bb);
        }
        const float4 o1 = x;

        // backward: start x and (stale) y are both E[ents[L]]
        const float4 yl = rows[L];
        x = yl;
        #pragma unroll
        for (int i = L - 1; i >= 0; i--) {
            float4 w  = *(const float4*)(sW + m[pp][i] * EMB + lane * 4);
            float4 bb = *(const float4*)(sB + m[pp][i] * EMB + lane * 4);
            x = relu_step(x, w, yl, bb);
        }

        const float c0 = cnt[pp];
        a1.x += c0 * o1.x; a1.y += c0 * o1.y; a1.z += c0 * o1.z; a1.w += c0 * o1.w;
        a2.x += c0 * x.x;  a2.y += c0 * x.y;  a2.z += c0 * x.z;  a2.w += c0 * x.w;
        cs   += c0;
    }

    ((float4*)sAcc[wid])[lane]         = a1;
    ((float4*)(sAcc[wid] + 128))[lane] = a2;
    if (lane == 0) sCnt[wid] = cs;
    __syncthreads();

    float s = 0.f, csum = 0.f;
    #pragma unroll
    for (int w = 0; w < 8; w++) { s += sAcc[w][tid]; csum += sCnt[w]; }
    g_H[(long)b * HDIM + gofs + tid] = s / csum;
}

// MLP head: MROWS=16 batch rows per block, 256 threads, 256 blocks.
// smem overlay: sH[16][768] (48 KB) for phase A, then reused for sh1/sh2.
__global__ __launch_bounds__(256) void mlp_kernel(
    const float* __restrict__ W1, const float* __restrict__ b1,
    const float* __restrict__ W2, const float* __restrict__ b2,
    const float* __restrict__ W3, const float* __restrict__ b3,
    float* __restrict__ out)
{
    __shared__ float smem[MROWS * HDIM];        // 48 KB
    float* const sH = smem;                     // [16][768] phase A
    // after phase A: sh1 = smem[0..2047]  ([16][128]), sh2 = smem[2048..2559]

    const int b0  = blockIdx.x * MROWS;
    const int tid = threadIdx.x;

    // Load full H tile: contiguous float4 copy (MROWS*HDIM/4 = 3072 float4)
    {
        const float4* src = (const float4*)(g_H + (long)b0 * HDIM);
        float4*       dst = (float4*)sH;
        #pragma unroll
        for (int i = 0; i < (MROWS * HDIM / 4) / 256; i++)
            dst[tid + i * 256] = src[tid + i * 256];
    }
    __syncthreads();

    // ── Phase A: h1 = relu(H @ W1 + b1), [16,128] ────────────────────────
    // thread = (col c = tid&127, row-half rh = tid>>7); 8 rows per thread.
    const int c     = tid & 127;
    const int rbase = (tid >> 7) * 8;
    float acc[8];
    {
        const float bias1 = b1[c];
        #pragma unroll
        for (int r = 0; r < 8; r++) acc[r] = bias1;
    }

    #pragma unroll 2
    for (int kb = 0; kb < HDIM; kb += 4) {
        const float* wp = W1 + kb * 128 + c;
        const float w0 = wp[0];
        const float w1 = wp[128];
        const float w2 = wp[256];
        const float w3 = wp[384];
        #pragma unroll
        for (int r = 0; r < 8; r++) {
            const float4 h = *(const float4*)(sH + (rbase + r) * HDIM + kb);
            float a = acc[r];
            a = fmaf(h.x, w0, a);
            a = fmaf(h.y, w1, a);
            a = fmaf(h.z, w2, a);
            a = fmaf(h.w, w3, a);
            acc[r] = a;
        }
    }
    __syncthreads();          // everyone done reading sH

    float* const sh1 = smem;                 // [16][128]
    float* const sh2 = smem + MROWS * 128;   // [16][32]
    #pragma unroll
    for (int r = 0; r < 8; r++)
        sh1[(rbase + r) * 128 + c] = fmaxf(acc[r], 0.f);
    __syncthreads();

    // ── Phase B: h2 = relu(h1 @ W2 + b2), [16,32] ───────────────────────
    {
        const int c2 = tid & 31;
        const int r0 = tid >> 5;   // 0..7 -> rows r0, r0+8
        #pragma unroll
        for (int rr = 0; rr < 2; rr++) {
            const int r = r0 + rr * 8;
            float a = b2[c2];
            #pragma unroll 4
            for (int k = 0; k < 128; k += 4) {
                const float4 h = *(const float4*)(sh1 + r * 128 + k);
                a = fmaf(h.x, W2[(k    ) * 32 + c2], a);
                a = fmaf(h.y, W2[(k + 1) * 32 + c2], a);
                a = fmaf(h.z, W2[(k + 2) * 32 + c2], a);
                a = fmaf(h.w, W2[(k + 3) * 32 + c2], a);
            }
            sh2[r * 32 + c2] = fmaxf(a, 0.f);
        }
    }
    __syncthreads();

    // ── Phase C: out = h2 @ W3 + b3, [16,1] ─────────────────────────────
    if (tid < MROWS) {
        float a = b3[0];
        #pragma unroll
        for (int k = 0; k < 32; k++) a = fmaf(sh2[tid * 32 + k], W3[k], a);
        out[b0 + tid] = a;
    }
}

extern "C" void kernel_launch(void* const* d_in, const int* in_sizes, int n_in,
                              void* d_out, int out_size)
{
    const bool dictOrder = (in_sizes[2] == BSZ * PSZ);

    const int *ent1, *mid1, *ent2, *mid2, *ent3, *mid3;
    const float *c1, *c2, *c3;
    if (dictOrder) {
        ent1 = (const int*)d_in[0]; mid1 = (const int*)d_in[1]; c1 = (const float*)d_in[2];
        ent2 = (const int*)d_in[3]; mid2 = (const int*)d_in[4]; c2 = (const float*)d_in[5];
        ent3 = (const int*)d_in[6]; mid3 = (const int*)d_in[7]; c3 = (const float*)d_in[8];
    } else {
        ent1 = (const int*)d_in[0]; mid1 = (const int*)d_in[1];
        ent2 = (const int*)d_in[2]; mid2 = (const int*)d_in[3];
        ent3 = (const int*)d_in[4]; mid3 = (const int*)d_in[5];
        c1 = (const float*)d_in[6]; c2 = (const float*)d_in[7]; c3 = (const float*)d_in[8];
    }
    const float* E  = (const float*)d_in[9];
    const float* Wm = (const float*)d_in[10];
    const float* Bm = (const float*)d_in[11];
    const float* W1 = (const float*)d_in[12];
    const float* b1 = (const float*)d_in[13];
    const float* W2 = (const float*)d_in[14];
    const float* b2 = (const float*)d_in[15];
    const float* W3 = (const float*)d_in[16];
    const float* b3 = (const float*)d_in[17];

    path_kernel<1><<<BSZ, 256>>>(ent1, mid1, c1, E, Wm, Bm, 0);
    path_kernel<2><<<BSZ, 256>>>(ent2, mid2, c2, E, Wm, Bm, 256);
    path_kernel<3><<<BSZ, 256>>>(ent3, mid3, c3, E, Wm, Bm, 512);
    mlp_kernel<<<BSZ / MROWS, 256>>>(W1, b1, W2, b2, W3, b3, (float*)d_out);
}

// round 4
// speedup vs baseline: 1.6129x; 1.1462x over previous
#include <cuda_runtime.h>

// Problem constants
#define BSZ   4096
#define PSZ   32
#define EMB   128
#define HDIM  768
#define MROWS 16            // batch rows per MLP block

// Scratch: intermediate H [B, 768] (12.6 MB)
__device__ float g_H[BSZ * HDIM];

__device__ __forceinline__ float4 relu_step(float4 x, float4 w, float4 y, float4 bm) {
    float4 r;
    r.x = fmaxf(fmaf(x.x * w.x, y.x, bm.x), 0.f);
    r.y = fmaxf(fmaf(x.y * w.y, y.y, bm.y), 0.f);
    r.z = fmaxf(fmaf(x.z * w.z, y.z, bm.z), 0.f);
    r.w = fmaxf(fmaf(x.w * w.w, y.w, bm.w), 0.f);
    return r;
}

struct PathSmem {
    float sW[3 * EMB];
    float sB[3 * EMB];
    float sAcc[8][256];
    float sCnt[8];
};

// One block per (batch row b, group). 8 warps; warp w handles paths
// p = w, w+8, w+16, w+24 with 1-path lookahead prefetch of embedding rows.
template<int L>
__device__ __forceinline__ void path_body(
    PathSmem& sm,
    const int*   __restrict__ ents,    // [B,P,L+1]
    const int*   __restrict__ mids,    // [B,P,L]
    const float* __restrict__ counts,  // [B,P]
    const float* __restrict__ E,       // [100000,128]
    const float* __restrict__ Wm,      // [3,128]
    const float* __restrict__ Bm,      // [3,128]
    int gofs)
{
    const int b    = blockIdx.x;
    const int tid  = threadIdx.x;
    const int wid  = tid >> 5;
    const int lane = tid & 31;

    for (int i = tid; i < 3 * EMB; i += 256) { sm.sW[i] = Wm[i]; sm.sB[i] = Bm[i]; }
    __syncthreads();

    // Hoist all indices + counts for this warp's 4 paths
    int   e[4][L + 1];
    int   m[4][L];
    float cnt[4];
    #pragma unroll
    for (int pp = 0; pp < 4; pp++) {
        const long base = (long)b * PSZ + (wid + pp * 8);
        const int* ep = ents + base * (L + 1);
        const int* mp = mids + base * L;
        #pragma unroll
        for (int i = 0; i <= L; i++) e[pp][i] = ep[i];
        #pragma unroll
        for (int i = 0; i < L; i++)  m[pp][i] = mp[i];
        cnt[pp] = counts[base];
    }

    float4 a1 = make_float4(0.f, 0.f, 0.f, 0.f);
    float4 a2 = make_float4(0.f, 0.f, 0.f, 0.f);
    float  cs = 0.f;

    // Double-buffered embedding-row gathers: buf[pp&1] = rows of path pp
    float4 buf[2][L + 1];
    #pragma unroll
    for (int i = 0; i <= L; i++)
        buf[0][i] = *(const float4*)(E + (long)e[0][i] * EMB + lane * 4);

    #pragma unroll
    for (int pp = 0; pp < 4; pp++) {
        if (pp < 3) {
            #pragma unroll
            for (int i = 0; i <= L; i++)
                buf[(pp + 1) & 1][i] =
                    *(const float4*)(E + (long)e[pp + 1][i] * EMB + lane * 4);
        }
        float4 (&rows)[L + 1] = buf[pp & 1];

        // forward
        float4 x = rows[0];
        #pragma unroll
        for (int i = 0; i < L; i++) {
            float4 w  = *(const float4*)(sm.sW + m[pp][i] * EMB + lane * 4);
            float4 bb = *(const float4*)(sm.sB + m[pp][i] * EMB + lane * 4);
            x = relu_step(x, w, rows[i + 1], bb);
        }
        const float4 o1 = x;

        // backward: start x and (stale) y are both E[ents[L]]
        const float4 yl = rows[L];
        x = yl;
        #pragma unroll
        for (int i = L - 1; i >= 0; i--) {
            float4 w  = *(const float4*)(sm.sW + m[pp][i] * EMB + lane * 4);
            float4 bb = *(const float4*)(sm.sB + m[pp][i] * EMB + lane * 4);
            x = relu_step(x, w, yl, bb);
        }

        const float c0 = cnt[pp];
        a1.x += c0 * o1.x; a1.y += c0 * o1.y; a1.z += c0 * o1.z; a1.w += c0 * o1.w;
        a2.x += c0 * x.x;  a2.y += c0 * x.y;  a2.z += c0 * x.z;  a2.w += c0 * x.w;
        cs   += c0;
    }

    ((float4*)sm.sAcc[wid])[lane]         = a1;
    ((float4*)(sm.sAcc[wid] + 128))[lane] = a2;
    if (lane == 0) sm.sCnt[wid] = cs;
    __syncthreads();

    float s = 0.f, csum = 0.f;
    #pragma unroll
    for (int w = 0; w < 8; w++) { s += sm.sAcc[w][tid]; csum += sm.sCnt[w]; }
    g_H[(long)b * HDIM + gofs + tid] = s / csum;
}

// Fused: all three groups in one launch. grid = (BSZ, 3), block = 256.
__global__ __launch_bounds__(256) void paths_kernel(
    const int* __restrict__ ent1, const int* __restrict__ mid1, const float* __restrict__ c1,
    const int* __restrict__ ent2, const int* __restrict__ mid2, const float* __restrict__ c2,
    const int* __restrict__ ent3, const int* __restrict__ mid3, const float* __restrict__ c3,
    const float* __restrict__ E, const float* __restrict__ Wm, const float* __restrict__ Bm)
{
    __shared__ PathSmem sm;
    const int g = blockIdx.y;
    if (g == 0)      path_body<1>(sm, ent1, mid1, c1, E, Wm, Bm, 0);
    else if (g == 1) path_body<2>(sm, ent2, mid2, c2, E, Wm, Bm, 256);
    else             path_body<3>(sm, ent3, mid3, c3, E, Wm, Bm, 512);
}

// MLP head: MROWS=16 rows per block, 512 threads (16 warps), 256 blocks.
// Phase A thread = (col c = tid&127, rgroup = tid>>7), 4 rows each.
__global__ __launch_bounds__(512) void mlp_kernel(
    const float* __restrict__ W1, const float* __restrict__ b1,
    const float* __restrict__ W2, const float* __restrict__ b2,
    const float* __restrict__ W3, const float* __restrict__ b3,
    float* __restrict__ out)
{
    __shared__ float smem[MROWS * HDIM];        // 48 KB exactly
    float* const sH = smem;

    const int b0  = blockIdx.x * MROWS;
    const int tid = threadIdx.x;

    // Load full H tile (3072 float4, 6 per thread)
    {
        const float4* src = (const float4*)(g_H + (long)b0 * HDIM);
        float4*       dst = (float4*)sH;
        #pragma unroll
        for (int i = 0; i < (MROWS * HDIM / 4) / 512; i++)
            dst[tid + i * 512] = src[tid + i * 512];
    }
    __syncthreads();

    // ── Phase A: h1 = relu(H @ W1 + b1), [16,128] ────────────────────────
    const int c     = tid & 127;
    const int rbase = (tid >> 7) * 4;     // 0,4,8,12
    float acc[4];
    {
        const float bias1 = b1[c];
        #pragma unroll
        for (int r = 0; r < 4; r++) acc[r] = bias1;
    }

    #pragma unroll 4
    for (int kb = 0; kb < HDIM; kb += 4) {
        const float* wp = W1 + kb * 128 + c;
        const float w0 = __ldg(wp);
        const float w1 = __ldg(wp + 128);
        const float w2 = __ldg(wp + 256);
        const float w3 = __ldg(wp + 384);
        #pragma unroll
        for (int r = 0; r < 4; r++) {
            const float4 h = *(const float4*)(sH + (rbase + r) * HDIM + kb);
            float a = acc[r];
            a = fmaf(h.x, w0, a);
            a = fmaf(h.y, w1, a);
            a = fmaf(h.z, w2, a);
            a = fmaf(h.w, w3, a);
            acc[r] = a;
        }
    }
    __syncthreads();          // everyone done reading sH

    float* const sh1 = smem;                 // [16][128]
    float* const sh2 = smem + MROWS * 128;   // [16][32]
    #pragma unroll
    for (int r = 0; r < 4; r++)
        sh1[(rbase + r) * 128 + c] = fmaxf(acc[r], 0.f);
    __syncthreads();

    // ── Phase B: h2 = relu(h1 @ W2 + b2), [16,32] — 512 thr = 16 rows × 32 cols
    {
        const int c2 = tid & 31;
        const int r  = tid >> 5;   // 0..15
        float a = b2[c2];
        #pragma unroll 8
        for (int k = 0; k < 128; k += 4) {
            const float4 h = *(const float4*)(sh1 + r * 128 + k);
            a = fmaf(h.x, __ldg(W2 + (k    ) * 32 + c2), a);
            a = fmaf(h.y, __ldg(W2 + (k + 1) * 32 + c2), a);
            a = fmaf(h.z, __ldg(W2 + (k + 2) * 32 + c2), a);
            a = fmaf(h.w, __ldg(W2 + (k + 3) * 32 + c2), a);
        }
        sh2[r * 32 + c2] = fmaxf(a, 0.f);
    }
    __syncthreads();

    // ── Phase C: out = h2 @ W3 + b3, [16,1] ─────────────────────────────
    if (tid < MROWS) {
        float a = b3[0];
        #pragma unroll
        for (int k = 0; k < 32; k++) a = fmaf(sh2[tid * 32 + k], W3[k], a);
        out[b0 + tid] = a;
    }
}

extern "C" void kernel_launch(void* const* d_in, const int* in_sizes, int n_in,
                              void* d_out, int out_size)
{
    const bool dictOrder = (in_sizes[2] == BSZ * PSZ);

    const int *ent1, *mid1, *ent2, *mid2, *ent3, *mid3;
    const float *c1, *c2, *c3;
    if (dictOrder) {
        ent1 = (const int*)d_in[0]; mid1 = (const int*)d_in[1]; c1 = (const float*)d_in[2];
        ent2 = (const int*)d_in[3]; mid2 = (const int*)d_in[4]; c2 = (const float*)d_in[5];
        ent3 = (const int*)d_in[6]; mid3 = (const int*)d_in[7]; c3 = (const float*)d_in[8];
    } else {
        ent1 = (const int*)d_in[0]; mid1 = (const int*)d_in[1];
        ent2 = (const int*)d_in[2]; mid2 = (const int*)d_in[3];
        ent3 = (const int*)d_in[4]; mid3 = (const int*)d_in[5];
        c1 = (const float*)d_in[6]; c2 = (const float*)d_in[7]; c3 = (const float*)d_in[8];
    }
    const float* E  = (const float*)d_in[9];
    const float* Wm = (const float*)d_in[10];
    const float* Bm = (const float*)d_in[11];
    const float* W1 = (const float*)d_in[12];
    const float* b1 = (const float*)d_in[13];
    const float* W2 = (const float*)d_in[14];
    const float* b2 = (const float*)d_in[15];
    const float* W3 = (const float*)d_in[16];
    const float* b3 = (const float*)d_in[17];

    dim3 pgrid(BSZ, 3);
    paths_kernel<<<pgrid, 256>>>(ent1, mid1, c1, ent2, mid2, c2, ent3, mid3, c3,
                                 E, Wm, Bm);
    mlp_kernel<<<BSZ / MROWS, 512>>>(W1, b1, W2, b2, W3, b3, (float*)d_out);
}